// round 2
// baseline (speedup 1.0000x reference)
#include <cuda_runtime.h>
#include <cstdint>
#include <cstdio>

// Problem constants (fixed by the dataset)
#define NF 128
#define NGRAPHS 10000
#define MAXM 500000
#define EPSBN 1e-5f

// ---------------- scratch (device globals; no allocs allowed) ----------------
__device__ float g_S[NGRAPHS * NF];          // segment sums
__device__ float g_P[NGRAPHS * NF];          // S @ W_lin
__device__ float g_T[NGRAPHS * NF];          // relu(BN(P))
__device__ float g_H1[(size_t)MAXM * NF];    // 256 MB intermediate
__device__ float g_sum0[NF], g_ss0[NF];      // BN0 stats (over P)
__device__ float g_sc0[NF], g_sh0[NF];       // BN0 scale/shift
__device__ float g_stat1[2 * NF];            // BN1 accumulated sum/sumsq (atomics)
__device__ float g_sc1[NF], g_sh1[NF];       // BN1 scale/shift

// ---------------- zero the accumulators (fresh every graph replay) -----------
__global__ void zero_kernel() {
    const int n1 = NGRAPHS * NF;
    for (int i = blockIdx.x * blockDim.x + threadIdx.x; i < n1 + 2 * NF;
         i += gridDim.x * blockDim.x) {
        if (i < n1) g_S[i] = 0.f;
        else        g_stat1[i - n1] = 0.f;
    }
}

// ---------------- segment sum, exploiting sorted batch ------------------------
// 128 threads (one per feature), 256 rows per block, run-length local accumulate,
// one atomicAdd per (segment run x column).
__global__ void seg_sum_kernel(const float* __restrict__ x,
                               const int* __restrict__ batch, int M) {
    const int j = threadIdx.x;
    int r0 = blockIdx.x * 256;
    int r1 = min(r0 + 256, M);
    float acc = 0.f;
    int cur = -1;
    for (int r = r0; r < r1; ++r) {
        int b = __ldg(&batch[r]);
        if (b != cur) {
            if (cur >= 0) atomicAdd(&g_S[(size_t)cur * NF + j], acc);
            acc = 0.f; cur = b;
        }
        acc += x[(size_t)r * NF + j];
    }
    if (cur >= 0) atomicAdd(&g_S[(size_t)cur * NF + j], acc);
}

// ---------------- column stats (small matrices) -------------------------------
__global__ void colstats_kernel(const float* __restrict__ X, int n,
                                float* __restrict__ sum, float* __restrict__ ss) {
    __shared__ float sh1[256], sh2[256];
    const int col = blockIdx.x;
    float s = 0.f, q = 0.f;
    for (int r = threadIdx.x; r < n; r += 256) {
        float v = X[(size_t)r * NF + col];
        s += v; q += v * v;
    }
    sh1[threadIdx.x] = s; sh2[threadIdx.x] = q;
    __syncthreads();
    for (int off = 128; off > 0; off >>= 1) {
        if (threadIdx.x < off) {
            sh1[threadIdx.x] += sh1[threadIdx.x + off];
            sh2[threadIdx.x] += sh2[threadIdx.x + off];
        }
        __syncthreads();
    }
    if (threadIdx.x == 0) { sum[col] = sh1[0]; ss[col] = sh2[0]; }
}

// ---------------- BN stats -> scale/shift -------------------------------------
__global__ void bn_prep_kernel(const float* __restrict__ sum, const float* __restrict__ ss,
                               float n, const float* __restrict__ g,
                               const float* __restrict__ b,
                               float* __restrict__ sc, float* __restrict__ sh) {
    const int c = threadIdx.x;
    float mu = sum[c] / n;
    float var = ss[c] / n - mu * mu;
    float rstd = rsqrtf(var + EPSBN);
    float s = rstd * g[c];
    sc[c] = s;
    sh[c] = b[c] - mu * s;
}

// ---------------- T = relu(BN(P)) ---------------------------------------------
__global__ void make_T_kernel() {
    int i = blockIdx.x * blockDim.x + threadIdx.x;
    if (i < NGRAPHS * NF) {
        int c = i & (NF - 1);
        g_T[i] = fmaxf(fmaf(g_P[i], g_sc0[c], g_sh0[c]), 0.f);
    }
}

// ---------------- tiled fp32 GEMM: C = f(A) @ W (+ bias) ----------------------
// MODE 0: A = Asrc                 -> C (no bias, no stats)        [P = S@W_lin]
// MODE 1: A = Asrc + T[batch]      -> C = A@W + bias, + col stats  [H1]
// MODE 2: A = relu(Asrc*sc + sh)   -> C = A@W + bias               [out]
// BM=128, BN=128, full K=128 in smem. 256 threads, 8x8 microtile.
template <int MODE>
__global__ void __launch_bounds__(256)
gemm128(const float* __restrict__ Asrc, const float* __restrict__ W,
        const float* __restrict__ bias, const float* __restrict__ Tm,
        const int* __restrict__ batch,
        const float* __restrict__ sc, const float* __restrict__ sh,
        float* __restrict__ C, float* __restrict__ stats, int M) {
    extern __shared__ float smem[];
    float* Ash = smem;                 // [128][132], stored as Ash[k][m]
    float* Wsh = smem + NF * 132;      // [128][128], Wsh[k][n]

    const int tid = threadIdx.x;
    const int tx = tid & 15, ty = tid >> 4;
    const int row0 = blockIdx.x * 128;

    // Load W tile (128x128 f32 = 4096 float4)
    {
        const float4* W4 = (const float4*)W;
        float4* Wsh4 = (float4*)Wsh;
#pragma unroll
        for (int i = 0; i < 16; ++i) Wsh4[tid + 256 * i] = W4[tid + 256 * i];
    }

    // Load A tile with per-mode transform; store transposed (Ash[k][m])
#pragma unroll
    for (int it = 0; it < 16; ++it) {
        int i = tid + 256 * it;
        int r = i >> 5;          // row within tile
        int q = i & 31;          // float4 index within row
        int row = row0 + r;
        float4 v = make_float4(0.f, 0.f, 0.f, 0.f);
        if (row < M) {
            v = ((const float4*)Asrc)[(size_t)row * 32 + q];
            if (MODE == 1) {
                int g = batch[row];
                float4 t = ((const float4*)Tm)[(size_t)g * 32 + q];
                v.x += t.x; v.y += t.y; v.z += t.z; v.w += t.w;
            } else if (MODE == 2) {
                float4 s4 = ((const float4*)sc)[q];
                float4 h4 = ((const float4*)sh)[q];
                v.x = fmaxf(fmaf(v.x, s4.x, h4.x), 0.f);
                v.y = fmaxf(fmaf(v.y, s4.y, h4.y), 0.f);
                v.z = fmaxf(fmaf(v.z, s4.z, h4.z), 0.f);
                v.w = fmaxf(fmaf(v.w, s4.w, h4.w), 0.f);
            }
        }
        int c = q * 4;
        Ash[(c + 0) * 132 + r] = v.x;
        Ash[(c + 1) * 132 + r] = v.y;
        Ash[(c + 2) * 132 + r] = v.z;
        Ash[(c + 3) * 132 + r] = v.w;
    }
    __syncthreads();

    float acc[8][8];
#pragma unroll
    for (int i = 0; i < 8; ++i)
#pragma unroll
        for (int j = 0; j < 8; ++j) acc[i][j] = 0.f;

    const int mb = ty * 8, nb = tx * 8;
#pragma unroll 8
    for (int k = 0; k < NF; ++k) {
        float a[8], b[8];
        float4 a0 = *(const float4*)&Ash[k * 132 + mb];
        float4 a1 = *(const float4*)&Ash[k * 132 + mb + 4];
        float4 b0 = *(const float4*)&Wsh[k * NF + nb];
        float4 b1 = *(const float4*)&Wsh[k * NF + nb + 4];
        a[0] = a0.x; a[1] = a0.y; a[2] = a0.z; a[3] = a0.w;
        a[4] = a1.x; a[5] = a1.y; a[6] = a1.z; a[7] = a1.w;
        b[0] = b0.x; b[1] = b0.y; b[2] = b0.z; b[3] = b0.w;
        b[4] = b1.x; b[5] = b1.y; b[6] = b1.z; b[7] = b1.w;
#pragma unroll
        for (int i = 0; i < 8; ++i)
#pragma unroll
            for (int j = 0; j < 8; ++j) acc[i][j] = fmaf(a[i], b[j], acc[i][j]);
    }

    // Epilogue
    float bl[8];
#pragma unroll
    for (int j = 0; j < 8; ++j) bl[j] = (MODE != 0) ? bias[nb + j] : 0.f;

    float cs[8], css[8];
#pragma unroll
    for (int j = 0; j < 8; ++j) { cs[j] = 0.f; css[j] = 0.f; }

#pragma unroll
    for (int i = 0; i < 8; ++i) {
        int row = row0 + mb + i;
        if (row < M) {
            float vals[8];
#pragma unroll
            for (int j = 0; j < 8; ++j) vals[j] = acc[i][j] + bl[j];
            if (MODE == 1) {
#pragma unroll
                for (int j = 0; j < 8; ++j) { cs[j] += vals[j]; css[j] += vals[j] * vals[j]; }
            }
            float4* dst = (float4*)&C[(size_t)row * NF + nb];
            dst[0] = make_float4(vals[0], vals[1], vals[2], vals[3]);
            dst[1] = make_float4(vals[4], vals[5], vals[6], vals[7]);
        }
    }

    if (MODE == 1) {
        // Block-level column reduction of sum/sumsq, then one atomicAdd per column.
        __syncthreads();   // done with GEMM smem
        float* s1 = smem;            // [16][128]
        float* s2 = smem + 16 * NF;  // [16][128]
#pragma unroll
        for (int j = 0; j < 8; ++j) {
            s1[ty * NF + nb + j] = cs[j];
            s2[ty * NF + nb + j] = css[j];
        }
        __syncthreads();
        if (tid < NF) {
            float a = 0.f, b = 0.f;
#pragma unroll
            for (int t = 0; t < 16; ++t) {
                a += s1[t * NF + tid];
                b += s2[t * NF + tid];
            }
            atomicAdd(&stats[tid], a);
            atomicAdd(&stats[NF + tid], b);
        }
    }
}

// ---------------- launcher ----------------------------------------------------
extern "C" void kernel_launch(void* const* d_in, const int* in_sizes, int n_in,
                              void* d_out, int out_size) {
    const float* x     = (const float*)d_in[0];
    // d_in[1] edge_index, d_in[2] edge_attr: unused by the reference computation
    const int*   batch = (const int*)d_in[3];   // JAX demotes int64->int32 (x64 disabled)
    const float* W_lin = (const float*)d_in[4];
    const float* bn_g  = (const float*)d_in[5];
    const float* bn_b  = (const float*)d_in[6];
    const float* W1    = (const float*)d_in[7];
    const float* b1    = (const float*)d_in[8];
    const float* bn1_g = (const float*)d_in[9];
    const float* bn1_b = (const float*)d_in[10];
    const float* W2    = (const float*)d_in[11];
    const float* b2    = (const float*)d_in[12];
    float*       out   = (float*)d_out;

    const int M = in_sizes[0] / NF;   // 500000

    float *pS, *pP, *pT, *pH1, *psum0, *pss0, *psc0, *psh0, *pstat1, *psc1, *psh1;
    cudaGetSymbolAddress((void**)&pS, g_S);
    cudaGetSymbolAddress((void**)&pP, g_P);
    cudaGetSymbolAddress((void**)&pT, g_T);
    cudaGetSymbolAddress((void**)&pH1, g_H1);
    cudaGetSymbolAddress((void**)&psum0, g_sum0);
    cudaGetSymbolAddress((void**)&pss0, g_ss0);
    cudaGetSymbolAddress((void**)&psc0, g_sc0);
    cudaGetSymbolAddress((void**)&psh0, g_sh0);
    cudaGetSymbolAddress((void**)&pstat1, g_stat1);
    cudaGetSymbolAddress((void**)&psc1, g_sc1);
    cudaGetSymbolAddress((void**)&psh1, g_sh1);

    const int smem = (NF * 132 + NF * NF) * (int)sizeof(float);   // 133,120 B
    cudaFuncSetAttribute(gemm128<0>, cudaFuncAttributeMaxDynamicSharedMemorySize, smem);
    cudaFuncSetAttribute(gemm128<1>, cudaFuncAttributeMaxDynamicSharedMemorySize, smem);
    cudaFuncSetAttribute(gemm128<2>, cudaFuncAttributeMaxDynamicSharedMemorySize, smem);

    // 1) zero accumulators
    zero_kernel<<<2500, 256>>>();

    // 2) segment sum  S = segment_sum(x, batch)
    seg_sum_kernel<<<(M + 255) / 256, 128>>>(x, batch, M);

    // 3) P = S @ W_lin
    gemm128<0><<<(NGRAPHS + 127) / 128, 256, smem>>>(
        pS, W_lin, nullptr, nullptr, nullptr, nullptr, nullptr, pP, nullptr, NGRAPHS);

    // 4) BN0 stats -> scale/shift, T = relu(BN(P))
    colstats_kernel<<<NF, 256>>>(pP, NGRAPHS, psum0, pss0);
    bn_prep_kernel<<<1, NF>>>(psum0, pss0, (float)NGRAPHS, bn_g, bn_b, psc0, psh0);
    make_T_kernel<<<(NGRAPHS * NF + 255) / 256, 256>>>();

    // 5) H1 = (x + T[batch]) @ W1 + b1, with fused column sum/sumsq
    gemm128<1><<<(M + 127) / 128, 256, smem>>>(
        x, W1, b1, pT, batch, nullptr, nullptr, pH1, pstat1, M);

    // 6) BN1 scale/shift
    bn_prep_kernel<<<1, NF>>>(pstat1, pstat1 + NF, (float)M, bn1_g, bn1_b, psc1, psh1);

    // 7) out = relu(BN(H1)) @ W2 + b2
    gemm128<2><<<(M + 127) / 128, 256, smem>>>(
        pH1, W2, b2, nullptr, nullptr, psc1, psh1, out, nullptr, M);
}

// round 4
// speedup vs baseline: 2.4817x; 2.4817x over previous
#include <cuda_runtime.h>
#include <cuda_bf16.h>
#include <cstdint>

// ---------------- problem constants ----------------
#define NF 128
#define NGRAPHS 10000
#define MAXM 500000
#define EPSBN 1e-5f
#define NTILES ((MAXM + 127) >> 7)   // 3907

// ---------------- scratch globals (no allocs allowed) ----------------
__device__ float g_S[NGRAPHS * NF];
__device__ float g_P[NGRAPHS * NF];
__device__ float g_T[NGRAPHS * NF];
__device__ float g_H1[(size_t)MAXM * NF];
__device__ float g_sum0[NF], g_ss0[NF];
__device__ float g_sc0[NF], g_sh0[NF];
__device__ float g_stat1[2 * NF];
__device__ float g_sc1[NF], g_sh1[NF];
// weight tiles, bf16 hi/lo, layout [k][n] with pitch 136 bf16 (272B/row), 34816B
__device__ uint4 g_w1hi[2176], g_w1lo[2176], g_w2hi[2176], g_w2lo[2176];

// ---------------- smem layout (dynamic) ----------------
// stage: 65536 (raw x tile, float4-swizzled)
// Ahi:   34816   Alo: 34816   Whi: 34816   Wlo: 34816
// params: bias/sc/sh 3*512
#define OFF_STAGE 0
#define OFF_AHI   65536
#define OFF_ALO   (65536 + 34816)
#define OFF_WHI   (65536 + 2 * 34816)
#define OFF_WLO   (65536 + 3 * 34816)
#define OFF_PRM   (65536 + 4 * 34816)
#define SMEM_MMA  (OFF_PRM + 3 * 512)   // 206,336 B

// ---------------- ptx helpers (sm_80-level only; no tcgen05!) ----------------
__device__ __forceinline__ void ldsm_x4(uint32_t* r, uint32_t addr) {
    asm volatile("ldmatrix.sync.aligned.m8n8.x4.shared.b16 {%0,%1,%2,%3}, [%4];"
                 : "=r"(r[0]), "=r"(r[1]), "=r"(r[2]), "=r"(r[3]) : "r"(addr));
}
__device__ __forceinline__ void ldsm_x4_t(uint32_t* r, uint32_t addr) {
    asm volatile("ldmatrix.sync.aligned.m8n8.x4.trans.shared.b16 {%0,%1,%2,%3}, [%4];"
                 : "=r"(r[0]), "=r"(r[1]), "=r"(r[2]), "=r"(r[3]) : "r"(addr));
}
__device__ __forceinline__ void mma_bf16(float* c, const uint32_t* a, const uint32_t* b) {
    asm volatile("mma.sync.aligned.m16n8k16.row.col.f32.bf16.bf16.f32 "
                 "{%0,%1,%2,%3}, {%4,%5,%6,%7}, {%8,%9}, {%0,%1,%2,%3};"
                 : "+f"(c[0]), "+f"(c[1]), "+f"(c[2]), "+f"(c[3])
                 : "r"(a[0]), "r"(a[1]), "r"(a[2]), "r"(a[3]), "r"(b[0]), "r"(b[1]));
}
__device__ __forceinline__ void cp16(uint32_t dst, const void* src, int sz) {
    asm volatile("cp.async.cg.shared.global [%0], [%1], 16, %2;"
                 :: "r"(dst), "l"(src), "r"(sz));
}
#define CP_COMMIT() asm volatile("cp.async.commit_group;")
#define CP_WAIT0()  asm volatile("cp.async.wait_group 0;")

// split fp32x4 -> bf16 hi/lo packed pairs
__device__ __forceinline__ void split4(float4 v, uint2& hi, uint2& lo) {
    __nv_bfloat16 h0 = __float2bfloat16(v.x), h1 = __float2bfloat16(v.y),
                  h2 = __float2bfloat16(v.z), h3 = __float2bfloat16(v.w);
    __nv_bfloat16 l0 = __float2bfloat16(v.x - __bfloat162float(h0));
    __nv_bfloat16 l1 = __float2bfloat16(v.y - __bfloat162float(h1));
    __nv_bfloat16 l2 = __float2bfloat16(v.z - __bfloat162float(h2));
    __nv_bfloat16 l3 = __float2bfloat16(v.w - __bfloat162float(h3));
    hi.x = (uint32_t)__bfloat16_as_ushort(h0) | ((uint32_t)__bfloat16_as_ushort(h1) << 16);
    hi.y = (uint32_t)__bfloat16_as_ushort(h2) | ((uint32_t)__bfloat16_as_ushort(h3) << 16);
    lo.x = (uint32_t)__bfloat16_as_ushort(l0) | ((uint32_t)__bfloat16_as_ushort(l1) << 16);
    lo.y = (uint32_t)__bfloat16_as_ushort(l2) | ((uint32_t)__bfloat16_as_ushort(l3) << 16);
}

// ---------------- misc small kernels ----------------
__global__ void zero_kernel() {
    const int n1 = NGRAPHS * NF;
    for (int i = blockIdx.x * blockDim.x + threadIdx.x; i < n1 + 2 * NF;
         i += gridDim.x * blockDim.x) {
        if (i < n1) g_S[i] = 0.f;
        else        g_stat1[i - n1] = 0.f;
    }
}

__global__ void seg_sum_kernel(const float* __restrict__ x,
                               const int* __restrict__ batch, int M) {
    const int j = threadIdx.x;
    int r0 = blockIdx.x * 256;
    int r1 = min(r0 + 256, M);
    float acc = 0.f;
    int cur = -1;
    for (int r = r0; r < r1; ++r) {
        int b = __ldg(&batch[r]);
        if (b != cur) {
            if (cur >= 0) atomicAdd(&g_S[(size_t)cur * NF + j], acc);
            acc = 0.f; cur = b;
        }
        acc += x[(size_t)r * NF + j];
    }
    if (cur >= 0) atomicAdd(&g_S[(size_t)cur * NF + j], acc);
}

__global__ void colstats_kernel(const float* __restrict__ X, int n,
                                float* __restrict__ sum, float* __restrict__ ss) {
    __shared__ float sh1[256], sh2[256];
    const int col = blockIdx.x;
    float s = 0.f, q = 0.f;
    for (int r = threadIdx.x; r < n; r += 256) {
        float v = X[(size_t)r * NF + col];
        s += v; q += v * v;
    }
    sh1[threadIdx.x] = s; sh2[threadIdx.x] = q;
    __syncthreads();
    for (int off = 128; off > 0; off >>= 1) {
        if (threadIdx.x < off) {
            sh1[threadIdx.x] += sh1[threadIdx.x + off];
            sh2[threadIdx.x] += sh2[threadIdx.x + off];
        }
        __syncthreads();
    }
    if (threadIdx.x == 0) { sum[col] = sh1[0]; ss[col] = sh2[0]; }
}

__global__ void bn_prep_kernel(const float* __restrict__ sum, const float* __restrict__ ss,
                               float n, const float* __restrict__ g,
                               const float* __restrict__ b,
                               float* __restrict__ sc, float* __restrict__ sh) {
    const int c = threadIdx.x;
    float mu = sum[c] / n;
    float var = ss[c] / n - mu * mu;
    float rstd = rsqrtf(var + EPSBN);
    float s = rstd * g[c];
    sc[c] = s;
    sh[c] = b[c] - mu * s;
}

__global__ void make_T_kernel() {
    int i = blockIdx.x * blockDim.x + threadIdx.x;
    if (i < NGRAPHS * NF) {
        int c = i & (NF - 1);
        g_T[i] = fmaxf(fmaf(g_P[i], g_sc0[c], g_sh0[c]), 0.f);
    }
}

// split W1, W2 into bf16 hi/lo tiles, layout [k][n] pitch 136 bf16
__global__ void wprep_kernel(const float* __restrict__ W1, const float* __restrict__ W2) {
    int i = blockIdx.x * 256 + threadIdx.x;
    if (i >= NF * NF) return;
    int k = i >> 7, n = i & 127;
    uint32_t off = (uint32_t)k * 272 + (uint32_t)n * 2;
    {
        float v = W1[i];
        __nv_bfloat16 h = __float2bfloat16(v);
        __nv_bfloat16 l = __float2bfloat16(v - __bfloat162float(h));
        *(unsigned short*)((unsigned char*)g_w1hi + off) = __bfloat16_as_ushort(h);
        *(unsigned short*)((unsigned char*)g_w1lo + off) = __bfloat16_as_ushort(l);
    }
    {
        float v = W2[i];
        __nv_bfloat16 h = __float2bfloat16(v);
        __nv_bfloat16 l = __float2bfloat16(v - __bfloat162float(h));
        *(unsigned short*)((unsigned char*)g_w2hi + off) = __bfloat16_as_ushort(h);
        *(unsigned short*)((unsigned char*)g_w2lo + off) = __bfloat16_as_ushort(l);
    }
}

// ---------------- fp32 GEMM for the tiny P = S @ W_lin ----------------
__global__ void __launch_bounds__(256)
gemm_small(const float* __restrict__ Asrc, const float* __restrict__ W,
           float* __restrict__ C, int M) {
    extern __shared__ float smemf[];
    float* Ash = smemf;                 // [128][132] transposed
    float* Wsh = smemf + NF * 132;
    const int tid = threadIdx.x;
    const int tx = tid & 15, ty = tid >> 4;
    const int row0 = blockIdx.x * 128;
    {
        const float4* W4 = (const float4*)W;
        float4* Wsh4 = (float4*)Wsh;
#pragma unroll
        for (int i = 0; i < 16; ++i) Wsh4[tid + 256 * i] = W4[tid + 256 * i];
    }
#pragma unroll
    for (int it = 0; it < 16; ++it) {
        int i = tid + 256 * it;
        int r = i >> 5, q = i & 31;
        int row = row0 + r;
        float4 v = make_float4(0.f, 0.f, 0.f, 0.f);
        if (row < M) v = ((const float4*)Asrc)[(size_t)row * 32 + q];
        int c = q * 4;
        Ash[(c + 0) * 132 + r] = v.x; Ash[(c + 1) * 132 + r] = v.y;
        Ash[(c + 2) * 132 + r] = v.z; Ash[(c + 3) * 132 + r] = v.w;
    }
    __syncthreads();
    float acc[8][8];
#pragma unroll
    for (int i = 0; i < 8; ++i)
#pragma unroll
        for (int j = 0; j < 8; ++j) acc[i][j] = 0.f;
    const int mb = ty * 8, nb = tx * 8;
#pragma unroll 8
    for (int k = 0; k < NF; ++k) {
        float a[8], b[8];
        float4 a0 = *(const float4*)&Ash[k * 132 + mb];
        float4 a1 = *(const float4*)&Ash[k * 132 + mb + 4];
        float4 b0 = *(const float4*)&Wsh[k * NF + nb];
        float4 b1 = *(const float4*)&Wsh[k * NF + nb + 4];
        a[0] = a0.x; a[1] = a0.y; a[2] = a0.z; a[3] = a0.w;
        a[4] = a1.x; a[5] = a1.y; a[6] = a1.z; a[7] = a1.w;
        b[0] = b0.x; b[1] = b0.y; b[2] = b0.z; b[3] = b0.w;
        b[4] = b1.x; b[5] = b1.y; b[6] = b1.z; b[7] = b1.w;
#pragma unroll
        for (int i = 0; i < 8; ++i)
#pragma unroll
            for (int j = 0; j < 8; ++j) acc[i][j] = fmaf(a[i], b[j], acc[i][j]);
    }
#pragma unroll
    for (int i = 0; i < 8; ++i) {
        int row = row0 + mb + i;
        if (row < M) {
            float4* dst = (float4*)&C[(size_t)row * NF + nb];
            dst[0] = make_float4(acc[i][0], acc[i][1], acc[i][2], acc[i][3]);
            dst[1] = make_float4(acc[i][4], acc[i][5], acc[i][6], acc[i][7]);
        }
    }
}

// ---------------- persistent HMMA (mma.sync bf16 split) GEMM ----------------
// MODE 1: C = (x + T[batch]) @ W + bias  (+ fused BN1 column stats)
// MODE 2: C = relu(Asrc*sc + sh) @ W + bias
template <int MODE>
__global__ void __launch_bounds__(256, 1)
gemm_mma(const float* __restrict__ Asrc,
         const uint4* __restrict__ Whi_g, const uint4* __restrict__ Wlo_g,
         const float* __restrict__ bias,
         const float* __restrict__ Tm, const int* __restrict__ batch,
         const float* __restrict__ sc, const float* __restrict__ sh,
         float* __restrict__ C, float* __restrict__ stats, int M) {
    extern __shared__ unsigned char sm[];
    float4* stage = (float4*)(sm + OFF_STAGE);
    float*  psm   = (float*)(sm + OFF_PRM);     // bias[128], sc[128], sh[128]
    const uint32_t sb = (uint32_t)__cvta_generic_to_shared(sm);

    const int tid = threadIdx.x;
    const int wid = tid >> 5, lane = tid & 31;
    const int tig = lane & 3, grp = lane >> 2;
    const int warp_m = wid >> 2, warp_n = wid & 3;

    // load params + W tiles (already bf16/pitch-136) into smem
    if (tid < NF) {
        psm[tid] = __ldg(&bias[tid]);
        if (MODE == 2) { psm[128 + tid] = __ldg(&sc[tid]); psm[256 + tid] = __ldg(&sh[tid]); }
    }
    {
        uint4* dh = (uint4*)(sm + OFF_WHI);
        uint4* dl = (uint4*)(sm + OFF_WLO);
        for (int i = tid; i < 2176; i += 256) {
            dh[i] = __ldg(&Whi_g[i]);
            dl[i] = __ldg(&Wlo_g[i]);
        }
    }

    // per-lane bias for epilogue columns
    float bias_r[4][2];
#pragma unroll
    for (int nt = 0; nt < 4; ++nt) {
        bias_r[nt][0] = __ldg(&bias[warp_n * 32 + nt * 8 + tig * 2]);
        bias_r[nt][1] = __ldg(&bias[warp_n * 32 + nt * 8 + tig * 2 + 1]);
    }

    float cs[4][2], cq[4][2];
    if (MODE == 1) {
#pragma unroll
        for (int nt = 0; nt < 4; ++nt) { cs[nt][0] = cs[nt][1] = 0.f; cq[nt][0] = cq[nt][1] = 0.f; }
    }

    // prologue loads for first tile
    const int t0 = blockIdx.x;
    {
        int tile = t0;
#pragma unroll
        for (int i = 0; i < 16; ++i) {
            int idx = tid + 256 * i;
            int r = idx >> 5, q = idx & 31;
            int rg = tile * 128 + r;
            const float4* src = (const float4*)Asrc + (size_t)min(rg, M - 1) * 32 + q;
            uint32_t dst = sb + OFF_STAGE + (uint32_t)(r * 32 + (q ^ (r & 31))) * 16;
            cp16(dst, src, rg < M ? 16 : 0);
        }
    }
    CP_COMMIT();

    const int row_l = tid >> 1;   // convert role: row within tile
    const int half  = tid & 1;    // which 64-col half

    for (int tile = t0; tile < NTILES; tile += gridDim.x) {
        CP_WAIT0();
        __syncthreads();

        // ---- convert stage -> Ahi/Alo (fused transform) ----
        {
            int rg = tile * 128 + row_l;
            const float4* trow = nullptr;
            if (MODE == 1) {
                int g = __ldg(&batch[min(rg, M - 1)]);
                trow = (const float4*)(Tm + (size_t)g * NF);
            }
            unsigned char* Ah = sm + OFF_AHI;
            unsigned char* Al = sm + OFF_ALO;
#pragma unroll
            for (int q = 0; q < 16; ++q) {
                int qq = half * 16 + q;            // float4 col idx 0..31
                float4 v = stage[row_l * 32 + (qq ^ (row_l & 31))];
                if (MODE == 1) {
                    float4 t = __ldg(trow + qq);
                    v.x += t.x; v.y += t.y; v.z += t.z; v.w += t.w;
                } else {
                    int k0 = qq * 4;
                    v.x = fmaxf(fmaf(v.x, psm[128 + k0 + 0], psm[256 + k0 + 0]), 0.f);
                    v.y = fmaxf(fmaf(v.y, psm[128 + k0 + 1], psm[256 + k0 + 1]), 0.f);
                    v.z = fmaxf(fmaf(v.z, psm[128 + k0 + 2], psm[256 + k0 + 2]), 0.f);
                    v.w = fmaxf(fmaf(v.w, psm[128 + k0 + 3], psm[256 + k0 + 3]), 0.f);
                }
                uint2 hi, lo;
                split4(v, hi, lo);
                uint32_t off = (uint32_t)row_l * 272 + (uint32_t)qq * 8;
                *(uint2*)(Ah + off) = hi;
                *(uint2*)(Al + off) = lo;
            }
        }
        __syncthreads();

        // ---- prefetch next tile into stage ----
        {
            int nt_ = tile + gridDim.x;
            if (nt_ < NTILES) {
#pragma unroll
                for (int i = 0; i < 16; ++i) {
                    int idx = tid + 256 * i;
                    int r = idx >> 5, q = idx & 31;
                    int rg = nt_ * 128 + r;
                    const float4* src = (const float4*)Asrc + (size_t)min(rg, M - 1) * 32 + q;
                    uint32_t dst = sb + OFF_STAGE + (uint32_t)(r * 32 + (q ^ (r & 31))) * 16;
                    cp16(dst, src, rg < M ? 16 : 0);
                }
            }
            CP_COMMIT();
        }

        // ---- HMMA mainloop: 3-chain bf16 split into fp32 acc ----
        float acc[4][4][4];
#pragma unroll
        for (int mt = 0; mt < 4; ++mt)
#pragma unroll
            for (int nt = 0; nt < 4; ++nt)
#pragma unroll
                for (int e = 0; e < 4; ++e) acc[mt][nt][e] = 0.f;

        const int lrow = lane & 15, lsel = lane >> 4;
#pragma unroll
        for (int kt = 0; kt < 8; ++kt) {
            const int k0 = kt * 16;
            uint32_t ahi[4][4], alo[4][4], whi[2][4], wlo[2][4];
#pragma unroll
            for (int mt = 0; mt < 4; ++mt) {
                int r = warp_m * 64 + mt * 16 + lrow;
                uint32_t a = sb + OFF_AHI + (uint32_t)r * 272 + (uint32_t)(k0 + lsel * 8) * 2;
                ldsm_x4(ahi[mt], a);
                ldsm_x4(alo[mt], a + (OFF_ALO - OFF_AHI));
            }
#pragma unroll
            for (int nb = 0; nb < 2; ++nb) {
                int n0 = warp_n * 32 + nb * 16;
                uint32_t a = sb + OFF_WHI + (uint32_t)(k0 + lrow) * 272 + (uint32_t)(n0 + lsel * 8) * 2;
                ldsm_x4_t(whi[nb], a);
                ldsm_x4_t(wlo[nb], a + (OFF_WLO - OFF_WHI));
            }
#pragma unroll
            for (int mt = 0; mt < 4; ++mt)
#pragma unroll
                for (int nt = 0; nt < 4; ++nt) {
                    const uint32_t* bh = &whi[nt >> 1][(nt & 1) * 2];
                    const uint32_t* bl = &wlo[nt >> 1][(nt & 1) * 2];
                    mma_bf16(acc[mt][nt], ahi[mt], bh);
                    mma_bf16(acc[mt][nt], ahi[mt], bl);
                    mma_bf16(acc[mt][nt], alo[mt], bh);
                }
        }

        // ---- epilogue: bias, store, fused stats ----
#pragma unroll
        for (int mt = 0; mt < 4; ++mt) {
            int r0 = tile * 128 + warp_m * 64 + mt * 16 + grp;
            int r1 = r0 + 8;
            bool v0 = r0 < M, v1 = r1 < M;
            float* p0 = C + (size_t)r0 * NF + warp_n * 32 + tig * 2;
            float* p1 = C + (size_t)r1 * NF + warp_n * 32 + tig * 2;
#pragma unroll
            for (int nt = 0; nt < 4; ++nt) {
                float c0 = acc[mt][nt][0] + bias_r[nt][0];
                float c1 = acc[mt][nt][1] + bias_r[nt][1];
                float c2 = acc[mt][nt][2] + bias_r[nt][0];
                float c3 = acc[mt][nt][3] + bias_r[nt][1];
                if (v0) {
                    *(float2*)(p0 + nt * 8) = make_float2(c0, c1);
                    if (MODE == 1) { cs[nt][0] += c0; cs[nt][1] += c1; cq[nt][0] += c0 * c0; cq[nt][1] += c1 * c1; }
                }
                if (v1) {
                    *(float2*)(p1 + nt * 8) = make_float2(c2, c3);
                    if (MODE == 1) { cs[nt][0] += c2; cs[nt][1] += c3; cq[nt][0] += c2 * c2; cq[nt][1] += c3 * c3; }
                }
            }
        }
    }

    // ---- stats flush (MODE 1) ----
    if (MODE == 1) {
        __syncthreads();    // stage free (no pending cp.async past last tile)
        float* cs_sm = (float*)(sm + OFF_STAGE);          // [8][32]
        float* cq_sm = cs_sm + 256;
#pragma unroll
        for (int nt = 0; nt < 4; ++nt)
#pragma unroll
            for (int par = 0; par < 2; ++par) {
                float s = cs[nt][par], q = cq[nt][par];
#pragma unroll
                for (int msk = 16; msk >= 4; msk >>= 1) {
                    s += __shfl_xor_sync(0xFFFFFFFFu, s, msk);
                    q += __shfl_xor_sync(0xFFFFFFFFu, q, msk);
                }
                if (lane < 4) {
                    cs_sm[wid * 32 + nt * 8 + tig * 2 + par] = s;
                    cq_sm[wid * 32 + nt * 8 + tig * 2 + par] = q;
                }
            }
        __syncthreads();
        if (tid < 128) {
            int col = tid;
            int wn = col >> 5, cl = col & 31;
            atomicAdd(&stats[col], cs_sm[wn * 32 + cl] + cs_sm[(wn + 4) * 32 + cl]);
        } else {
            int col = tid - 128;
            int wn = col >> 5, cl = col & 31;
            atomicAdd(&stats[NF + col], cq_sm[wn * 32 + cl] + cq_sm[(wn + 4) * 32 + cl]);
        }
    }
}

// ---------------- launcher ----------------
extern "C" void kernel_launch(void* const* d_in, const int* in_sizes, int n_in,
                              void* d_out, int out_size) {
    const float* x     = (const float*)d_in[0];
    const int*   batch = (const int*)d_in[3];
    const float* W_lin = (const float*)d_in[4];
    const float* bn_g  = (const float*)d_in[5];
    const float* bn_b  = (const float*)d_in[6];
    const float* W1    = (const float*)d_in[7];
    const float* b1    = (const float*)d_in[8];
    const float* bn1_g = (const float*)d_in[9];
    const float* bn1_b = (const float*)d_in[10];
    const float* W2    = (const float*)d_in[11];
    const float* b2    = (const float*)d_in[12];
    float*       out   = (float*)d_out;

    const int M = in_sizes[0] / NF;   // 500000

    float *pS, *pP, *pT, *pH1, *psum0, *pss0, *psc0, *psh0, *pstat1, *psc1, *psh1;
    cudaGetSymbolAddress((void**)&pS, g_S);
    cudaGetSymbolAddress((void**)&pP, g_P);
    cudaGetSymbolAddress((void**)&pT, g_T);
    cudaGetSymbolAddress((void**)&pH1, g_H1);
    cudaGetSymbolAddress((void**)&psum0, g_sum0);
    cudaGetSymbolAddress((void**)&pss0, g_ss0);
    cudaGetSymbolAddress((void**)&psc0, g_sc0);
    cudaGetSymbolAddress((void**)&psh0, g_sh0);
    cudaGetSymbolAddress((void**)&pstat1, g_stat1);
    cudaGetSymbolAddress((void**)&psc1, g_sc1);
    cudaGetSymbolAddress((void**)&psh1, g_sh1);
    uint4 *pw1h, *pw1l, *pw2h, *pw2l;
    cudaGetSymbolAddress((void**)&pw1h, g_w1hi);
    cudaGetSymbolAddress((void**)&pw1l, g_w1lo);
    cudaGetSymbolAddress((void**)&pw2h, g_w2hi);
    cudaGetSymbolAddress((void**)&pw2l, g_w2lo);

    int dev = 0, nsm = 148;
    cudaGetDevice(&dev);
    cudaDeviceGetAttribute(&nsm, cudaDevAttrMultiProcessorCount, dev);

    const int smem_small = (NF * 132 + NF * NF) * (int)sizeof(float);
    cudaFuncSetAttribute(gemm_small, cudaFuncAttributeMaxDynamicSharedMemorySize, smem_small);
    cudaFuncSetAttribute(gemm_mma<1>, cudaFuncAttributeMaxDynamicSharedMemorySize, SMEM_MMA);
    cudaFuncSetAttribute(gemm_mma<2>, cudaFuncAttributeMaxDynamicSharedMemorySize, SMEM_MMA);

    // 1) zero accumulators; split+layout weights
    zero_kernel<<<2500, 256>>>();
    wprep_kernel<<<(NF * NF + 255) / 256, 256>>>(W1, W2);
    // 2) segment sum
    seg_sum_kernel<<<(M + 255) / 256, 128>>>(x, batch, M);
    // 3) P = S @ W_lin
    gemm_small<<<(NGRAPHS + 127) / 128, 256, smem_small>>>(pS, W_lin, pP, NGRAPHS);
    // 4) BN0 -> T
    colstats_kernel<<<NF, 256>>>(pP, NGRAPHS, psum0, pss0);
    bn_prep_kernel<<<1, NF>>>(psum0, pss0, (float)NGRAPHS, bn_g, bn_b, psc0, psh0);
    make_T_kernel<<<(NGRAPHS * NF + 255) / 256, 256>>>();
    // 5) H1 = (x + T[batch]) @ W1 + b1  (HMMA, fused BN1 stats)
    gemm_mma<1><<<nsm, 256, SMEM_MMA>>>(x, pw1h, pw1l, b1, pT, batch,
                                        nullptr, nullptr, pH1, pstat1, M);
    // 6) BN1 scale/shift
    bn_prep_kernel<<<1, NF>>>(pstat1, pstat1 + NF, (float)M, bn1_g, bn1_b, psc1, psh1);
    // 7) out = relu(BN(H1)) @ W2 + b2  (HMMA)
    gemm_mma<2><<<nsm, 256, SMEM_MMA>>>(pH1, pw2h, pw2l, b2, nullptr, nullptr,
                                        psc1, psh1, out, nullptr, M);
}

// round 5
// speedup vs baseline: 2.7779x; 1.1194x over previous
#include <cuda_runtime.h>
#include <cuda_bf16.h>
#include <cstdint>

// ---------------- problem constants ----------------
#define NF 128
#define NGRAPHS 10000
#define MAXM 500000
#define EPSBN 1e-5f

// ---------------- scratch globals (no allocs allowed) ----------------
__device__ float g_S[NGRAPHS * NF];
__device__ float g_P[NGRAPHS * NF];
__device__ float g_T[NGRAPHS * NF];
__device__ float g_H1[(size_t)MAXM * NF];
__device__ float g_stat0[2 * NF];            // BN0 sum/sumsq (atomics)
__device__ float g_sc0[NF], g_sh0[NF];
__device__ float g_stat1[2 * NF];            // BN1 sum/sumsq (atomics)
__device__ float g_sc1[NF], g_sh1[NF];
// weight tiles, bf16 hi/lo, layout [k][n] with pitch 136 bf16 (272B/row), 34816B
__device__ uint4 g_wlhi[2176], g_wllo[2176];
__device__ uint4 g_w1hi[2176], g_w1lo[2176], g_w2hi[2176], g_w2lo[2176];

// ---------------- smem layout (dynamic) ----------------
#define OFF_STAGE 0
#define OFF_AHI   65536
#define OFF_ALO   (65536 + 34816)
#define OFF_WHI   (65536 + 2 * 34816)
#define OFF_WLO   (65536 + 3 * 34816)
#define OFF_PRM   (65536 + 4 * 34816)
#define SMEM_MMA  (OFF_PRM + 3 * 512)   // 206,336 B

// ---------------- ptx helpers (sm_80-level only; no tcgen05!) ----------------
__device__ __forceinline__ void ldsm_x4(uint32_t* r, uint32_t addr) {
    asm volatile("ldmatrix.sync.aligned.m8n8.x4.shared.b16 {%0,%1,%2,%3}, [%4];"
                 : "=r"(r[0]), "=r"(r[1]), "=r"(r[2]), "=r"(r[3]) : "r"(addr));
}
__device__ __forceinline__ void ldsm_x4_t(uint32_t* r, uint32_t addr) {
    asm volatile("ldmatrix.sync.aligned.m8n8.x4.trans.shared.b16 {%0,%1,%2,%3}, [%4];"
                 : "=r"(r[0]), "=r"(r[1]), "=r"(r[2]), "=r"(r[3]) : "r"(addr));
}
__device__ __forceinline__ void mma_bf16(float* c, const uint32_t* a, const uint32_t* b) {
    asm volatile("mma.sync.aligned.m16n8k16.row.col.f32.bf16.bf16.f32 "
                 "{%0,%1,%2,%3}, {%4,%5,%6,%7}, {%8,%9}, {%0,%1,%2,%3};"
                 : "+f"(c[0]), "+f"(c[1]), "+f"(c[2]), "+f"(c[3])
                 : "r"(a[0]), "r"(a[1]), "r"(a[2]), "r"(a[3]), "r"(b[0]), "r"(b[1]));
}
__device__ __forceinline__ void cp16(uint32_t dst, const void* src, int sz) {
    asm volatile("cp.async.cg.shared.global [%0], [%1], 16, %2;"
                 :: "r"(dst), "l"(src), "r"(sz));
}
#define CP_COMMIT() asm volatile("cp.async.commit_group;")
#define CP_WAIT0()  asm volatile("cp.async.wait_group 0;")

// fast split: hi = truncated top-16 bits (PRMT pack), lo = rn-bf16 of residual
__device__ __forceinline__ void split4(float4 v, uint2& hi, uint2& lo) {
    uint32_t u0 = __float_as_uint(v.x), u1 = __float_as_uint(v.y),
             u2 = __float_as_uint(v.z), u3 = __float_as_uint(v.w);
    asm("prmt.b32 %0, %1, %2, 0x7632;" : "=r"(hi.x) : "r"(u0), "r"(u1));
    asm("prmt.b32 %0, %1, %2, 0x7632;" : "=r"(hi.y) : "r"(u2), "r"(u3));
    float l0 = v.x - __uint_as_float(u0 & 0xFFFF0000u);
    float l1 = v.y - __uint_as_float(u1 & 0xFFFF0000u);
    float l2 = v.z - __uint_as_float(u2 & 0xFFFF0000u);
    float l3 = v.w - __uint_as_float(u3 & 0xFFFF0000u);
    asm("cvt.rn.bf16x2.f32 %0, %1, %2;" : "=r"(lo.x) : "f"(l1), "f"(l0));
    asm("cvt.rn.bf16x2.f32 %0, %1, %2;" : "=r"(lo.y) : "f"(l3), "f"(l2));
}

// ---------------- misc small kernels ----------------
__global__ void zero_kernel() {
    const int n1 = NGRAPHS * NF;
    const int ntot = n1 + 4 * NF;
    for (int i = blockIdx.x * blockDim.x + threadIdx.x; i < ntot;
         i += gridDim.x * blockDim.x) {
        if (i < n1)               g_S[i] = 0.f;
        else if (i < n1 + 2 * NF) g_stat0[i - n1] = 0.f;
        else                      g_stat1[i - n1 - 2 * NF] = 0.f;
    }
}

// float4 lanes: 32 threads/row, 4 row-lanes, run-length accumulate per lane
__global__ void seg_sum_kernel(const float* __restrict__ x,
                               const int* __restrict__ batch, int M) {
    const int rg = threadIdx.x >> 5;   // row lane 0..3
    const int c4 = threadIdx.x & 31;   // float4 column
    int r0 = blockIdx.x * 256;
    int rend = min(r0 + 256, M);
    float4 acc = make_float4(0.f, 0.f, 0.f, 0.f);
    int cur = -1;
    for (int r = r0 + rg; r < rend; r += 4) {
        int b = __ldg(&batch[r]);
        if (b != cur) {
            if (cur >= 0) {
                float* d = &g_S[(size_t)cur * NF + c4 * 4];
                atomicAdd(d + 0, acc.x); atomicAdd(d + 1, acc.y);
                atomicAdd(d + 2, acc.z); atomicAdd(d + 3, acc.w);
            }
            acc = make_float4(0.f, 0.f, 0.f, 0.f); cur = b;
        }
        float4 v = __ldg((const float4*)x + (size_t)r * 32 + c4);
        acc.x += v.x; acc.y += v.y; acc.z += v.z; acc.w += v.w;
    }
    if (cur >= 0) {
        float* d = &g_S[(size_t)cur * NF + c4 * 4];
        atomicAdd(d + 0, acc.x); atomicAdd(d + 1, acc.y);
        atomicAdd(d + 2, acc.z); atomicAdd(d + 3, acc.w);
    }
}

__global__ void bn_prep_kernel(const float* __restrict__ sum, const float* __restrict__ ss,
                               float n, const float* __restrict__ g,
                               const float* __restrict__ b,
                               float* __restrict__ sc, float* __restrict__ sh) {
    const int c = threadIdx.x;
    float mu = sum[c] / n;
    float var = ss[c] / n - mu * mu;
    float rstd = rsqrtf(var + EPSBN);
    float s = rstd * g[c];
    sc[c] = s;
    sh[c] = b[c] - mu * s;
}

__global__ void make_T_kernel() {
    int i = blockIdx.x * blockDim.x + threadIdx.x;
    if (i < NGRAPHS * NF) {
        int c = i & (NF - 1);
        g_T[i] = fmaxf(fmaf(g_P[i], g_sc0[c], g_sh0[c]), 0.f);
    }
}

// split W_lin, W1, W2 into bf16 hi/lo tiles, layout [k][n] pitch 136 bf16
__global__ void wprep_kernel(const float* __restrict__ WL,
                             const float* __restrict__ W1,
                             const float* __restrict__ W2) {
    int i = blockIdx.x * 256 + threadIdx.x;
    if (i >= NF * NF) return;
    int k = i >> 7, n = i & 127;
    uint32_t off = (uint32_t)k * 272 + (uint32_t)n * 2;
    {
        float v = WL[i];
        __nv_bfloat16 h = __float2bfloat16(v);
        __nv_bfloat16 l = __float2bfloat16(v - __bfloat162float(h));
        *(unsigned short*)((unsigned char*)g_wlhi + off) = __bfloat16_as_ushort(h);
        *(unsigned short*)((unsigned char*)g_wllo + off) = __bfloat16_as_ushort(l);
    }
    {
        float v = W1[i];
        __nv_bfloat16 h = __float2bfloat16(v);
        __nv_bfloat16 l = __float2bfloat16(v - __bfloat162float(h));
        *(unsigned short*)((unsigned char*)g_w1hi + off) = __bfloat16_as_ushort(h);
        *(unsigned short*)((unsigned char*)g_w1lo + off) = __bfloat16_as_ushort(l);
    }
    {
        float v = W2[i];
        __nv_bfloat16 h = __float2bfloat16(v);
        __nv_bfloat16 l = __float2bfloat16(v - __bfloat162float(h));
        *(unsigned short*)((unsigned char*)g_w2hi + off) = __bfloat16_as_ushort(h);
        *(unsigned short*)((unsigned char*)g_w2lo + off) = __bfloat16_as_ushort(l);
    }
}

// ---------------- persistent HMMA (mma.sync bf16 split) GEMM ----------------
// MODE 0: C = Asrc @ W                       (+ fused BN0 column stats)
// MODE 1: C = (x + T[batch]) @ W + bias      (+ fused BN1 column stats)
// MODE 2: C = relu(Asrc*sc + sh) @ W + bias
template <int MODE>
__global__ void __launch_bounds__(256, 1)
gemm_mma(const float* __restrict__ Asrc,
         const uint4* __restrict__ Whi_g, const uint4* __restrict__ Wlo_g,
         const float* __restrict__ bias,
         const float* __restrict__ Tm, const int* __restrict__ batch,
         const float* __restrict__ sc, const float* __restrict__ sh,
         float* __restrict__ C, float* __restrict__ stats, int M, int ntiles) {
    constexpr bool STATS = (MODE != 2);
    constexpr bool HASBIAS = (MODE != 0);

    extern __shared__ unsigned char sm[];
    float4* stage = (float4*)(sm + OFF_STAGE);
    float*  psm   = (float*)(sm + OFF_PRM);     // bias[128], sc[128], sh[128]
    const uint32_t sb = (uint32_t)__cvta_generic_to_shared(sm);

    const int tid = threadIdx.x;
    const int wid = tid >> 5, lane = tid & 31;
    const int tig = lane & 3, grp = lane >> 2;
    const int warp_m = wid >> 2, warp_n = wid & 3;

    if (tid < NF) {
        psm[tid] = HASBIAS ? __ldg(&bias[tid]) : 0.f;
        if (MODE == 2) { psm[128 + tid] = __ldg(&sc[tid]); psm[256 + tid] = __ldg(&sh[tid]); }
    }
    {
        uint4* dh = (uint4*)(sm + OFF_WHI);
        uint4* dl = (uint4*)(sm + OFF_WLO);
        for (int i = tid; i < 2176; i += 256) {
            dh[i] = __ldg(&Whi_g[i]);
            dl[i] = __ldg(&Wlo_g[i]);
        }
    }

    float bias_r[4][2];
#pragma unroll
    for (int nt = 0; nt < 4; ++nt) {
        bias_r[nt][0] = HASBIAS ? __ldg(&bias[warp_n * 32 + nt * 8 + tig * 2]) : 0.f;
        bias_r[nt][1] = HASBIAS ? __ldg(&bias[warp_n * 32 + nt * 8 + tig * 2 + 1]) : 0.f;
    }

    float cs[4][2], cq[4][2];
    if (STATS) {
#pragma unroll
        for (int nt = 0; nt < 4; ++nt) { cs[nt][0] = cs[nt][1] = 0.f; cq[nt][0] = cq[nt][1] = 0.f; }
    }

    // prologue loads for first tile
    const int t0 = blockIdx.x;
    {
#pragma unroll
        for (int i = 0; i < 16; ++i) {
            int idx = tid + 256 * i;
            int r = idx >> 5, q = idx & 31;
            int rg = t0 * 128 + r;
            const float4* src = (const float4*)Asrc + (size_t)min(rg, M - 1) * 32 + q;
            uint32_t dst = sb + OFF_STAGE + (uint32_t)(r * 32 + (q ^ (r & 31))) * 16;
            cp16(dst, src, rg < M ? 16 : 0);
        }
    }
    CP_COMMIT();

    const int row_l = tid >> 1;   // convert role: row within tile
    const int half  = tid & 1;    // which 64-col half

    for (int tile = t0; tile < ntiles; tile += gridDim.x) {
        CP_WAIT0();
        __syncthreads();

        // ---- convert stage -> Ahi/Alo (fused transform) ----
        {
            int rg = tile * 128 + row_l;
            const float4* trow = nullptr;
            if (MODE == 1) {
                int g = __ldg(&batch[min(rg, M - 1)]);
                trow = (const float4*)(Tm + (size_t)g * NF);
            }
            unsigned char* Ah = sm + OFF_AHI;
            unsigned char* Al = sm + OFF_ALO;
#pragma unroll
            for (int q = 0; q < 16; ++q) {
                int qq = half * 16 + q;            // float4 col idx 0..31
                float4 v = stage[row_l * 32 + (qq ^ (row_l & 31))];
                if (MODE == 1) {
                    float4 t = __ldg(trow + qq);
                    v.x += t.x; v.y += t.y; v.z += t.z; v.w += t.w;
                } else if (MODE == 2) {
                    int k0 = qq * 4;
                    v.x = fmaxf(fmaf(v.x, psm[128 + k0 + 0], psm[256 + k0 + 0]), 0.f);
                    v.y = fmaxf(fmaf(v.y, psm[128 + k0 + 1], psm[256 + k0 + 1]), 0.f);
                    v.z = fmaxf(fmaf(v.z, psm[128 + k0 + 2], psm[256 + k0 + 2]), 0.f);
                    v.w = fmaxf(fmaf(v.w, psm[128 + k0 + 3], psm[256 + k0 + 3]), 0.f);
                }
                uint2 hi, lo;
                split4(v, hi, lo);
                uint32_t off = (uint32_t)row_l * 272 + (uint32_t)qq * 8;
                *(uint2*)(Ah + off) = hi;
                *(uint2*)(Al + off) = lo;
            }
        }
        __syncthreads();

        // ---- prefetch next tile into stage ----
        {
            int nt_ = tile + gridDim.x;
            if (nt_ < ntiles) {
#pragma unroll
                for (int i = 0; i < 16; ++i) {
                    int idx = tid + 256 * i;
                    int r = idx >> 5, q = idx & 31;
                    int rg = nt_ * 128 + r;
                    const float4* src = (const float4*)Asrc + (size_t)min(rg, M - 1) * 32 + q;
                    uint32_t dst = sb + OFF_STAGE + (uint32_t)(r * 32 + (q ^ (r & 31))) * 16;
                    cp16(dst, src, rg < M ? 16 : 0);
                }
            }
            CP_COMMIT();
        }

        // ---- HMMA mainloop: 3-chain bf16 split into fp32 acc ----
        float acc[4][4][4];
#pragma unroll
        for (int mt = 0; mt < 4; ++mt)
#pragma unroll
            for (int nt = 0; nt < 4; ++nt)
#pragma unroll
                for (int e = 0; e < 4; ++e) acc[mt][nt][e] = 0.f;

        const int lrow = lane & 15, lsel = lane >> 4;
#pragma unroll
        for (int kt = 0; kt < 8; ++kt) {
            const int k0 = kt * 16;
            uint32_t ahi[4][4], alo[4][4], whi[2][4], wlo[2][4];
#pragma unroll
            for (int mt = 0; mt < 4; ++mt) {
                int r = warp_m * 64 + mt * 16 + lrow;
                uint32_t a = sb + OFF_AHI + (uint32_t)r * 272 + (uint32_t)(k0 + lsel * 8) * 2;
                ldsm_x4(ahi[mt], a);
                ldsm_x4(alo[mt], a + (OFF_ALO - OFF_AHI));
            }
#pragma unroll
            for (int nb = 0; nb < 2; ++nb) {
                int n0 = warp_n * 32 + nb * 16;
                uint32_t a = sb + OFF_WHI + (uint32_t)(k0 + lrow) * 272 + (uint32_t)(n0 + lsel * 8) * 2;
                ldsm_x4_t(whi[nb], a);
                ldsm_x4_t(wlo[nb], a + (OFF_WLO - OFF_WHI));
            }
#pragma unroll
            for (int mt = 0; mt < 4; ++mt)
#pragma unroll
                for (int nt = 0; nt < 4; ++nt) {
                    const uint32_t* bh = &whi[nt >> 1][(nt & 1) * 2];
                    const uint32_t* bl = &wlo[nt >> 1][(nt & 1) * 2];
                    mma_bf16(acc[mt][nt], ahi[mt], bh);
                    mma_bf16(acc[mt][nt], ahi[mt], bl);
                    mma_bf16(acc[mt][nt], alo[mt], bh);
                }
        }

        // ---- epilogue: bias, store, fused stats ----
#pragma unroll
        for (int mt = 0; mt < 4; ++mt) {
            int r0 = tile * 128 + warp_m * 64 + mt * 16 + grp;
            int r1 = r0 + 8;
            bool v0 = r0 < M, v1 = r1 < M;
            float* p0 = C + (size_t)r0 * NF + warp_n * 32 + tig * 2;
            float* p1 = C + (size_t)r1 * NF + warp_n * 32 + tig * 2;
#pragma unroll
            for (int nt = 0; nt < 4; ++nt) {
                float c0 = acc[mt][nt][0] + bias_r[nt][0];
                float c1 = acc[mt][nt][1] + bias_r[nt][1];
                float c2 = acc[mt][nt][2] + bias_r[nt][0];
                float c3 = acc[mt][nt][3] + bias_r[nt][1];
                if (v0) {
                    *(float2*)(p0 + nt * 8) = make_float2(c0, c1);
                    if (STATS) { cs[nt][0] += c0; cs[nt][1] += c1; cq[nt][0] += c0 * c0; cq[nt][1] += c1 * c1; }
                }
                if (v1) {
                    *(float2*)(p1 + nt * 8) = make_float2(c2, c3);
                    if (STATS) { cs[nt][0] += c2; cs[nt][1] += c3; cq[nt][0] += c2 * c2; cq[nt][1] += c3 * c3; }
                }
            }
        }
    }

    // ---- stats flush ----
    if (STATS) {
        CP_WAIT0();         // drain any pending prologue copies into stage
        __syncthreads();    // stage now free for reuse
        float* cs_sm = (float*)(sm + OFF_STAGE);          // [8][32]
        float* cq_sm = cs_sm + 256;
#pragma unroll
        for (int nt = 0; nt < 4; ++nt)
#pragma unroll
            for (int par = 0; par < 2; ++par) {
                float s = cs[nt][par], q = cq[nt][par];
#pragma unroll
                for (int msk = 16; msk >= 4; msk >>= 1) {
                    s += __shfl_xor_sync(0xFFFFFFFFu, s, msk);
                    q += __shfl_xor_sync(0xFFFFFFFFu, q, msk);
                }
                if (lane < 4) {
                    cs_sm[wid * 32 + nt * 8 + tig * 2 + par] = s;
                    cq_sm[wid * 32 + nt * 8 + tig * 2 + par] = q;
                }
            }
        __syncthreads();
        if (tid < 128) {
            int col = tid;
            int wn = col >> 5, cl = col & 31;
            atomicAdd(&stats[col], cs_sm[wn * 32 + cl] + cs_sm[(wn + 4) * 32 + cl]);
        } else {
            int col = tid - 128;
            int wn = col >> 5, cl = col & 31;
            atomicAdd(&stats[NF + col], cq_sm[wn * 32 + cl] + cq_sm[(wn + 4) * 32 + cl]);
        }
    }
}

// ---------------- launcher ----------------
extern "C" void kernel_launch(void* const* d_in, const int* in_sizes, int n_in,
                              void* d_out, int out_size) {
    const float* x     = (const float*)d_in[0];
    const int*   batch = (const int*)d_in[3];
    const float* W_lin = (const float*)d_in[4];
    const float* bn_g  = (const float*)d_in[5];
    const float* bn_b  = (const float*)d_in[6];
    const float* W1    = (const float*)d_in[7];
    const float* b1    = (const float*)d_in[8];
    const float* bn1_g = (const float*)d_in[9];
    const float* bn1_b = (const float*)d_in[10];
    const float* W2    = (const float*)d_in[11];
    const float* b2    = (const float*)d_in[12];
    float*       out   = (float*)d_out;

    const int M = in_sizes[0] / NF;   // 500000
    const int ntiles_big = (M + 127) / 128;
    const int ntiles_sml = (NGRAPHS + 127) / 128;   // 79

    float *pS, *pP, *pT, *pH1, *pstat0, *psc0, *psh0, *pstat1, *psc1, *psh1;
    cudaGetSymbolAddress((void**)&pS, g_S);
    cudaGetSymbolAddress((void**)&pP, g_P);
    cudaGetSymbolAddress((void**)&pT, g_T);
    cudaGetSymbolAddress((void**)&pH1, g_H1);
    cudaGetSymbolAddress((void**)&pstat0, g_stat0);
    cudaGetSymbolAddress((void**)&psc0, g_sc0);
    cudaGetSymbolAddress((void**)&psh0, g_sh0);
    cudaGetSymbolAddress((void**)&pstat1, g_stat1);
    cudaGetSymbolAddress((void**)&psc1, g_sc1);
    cudaGetSymbolAddress((void**)&psh1, g_sh1);
    uint4 *pwlh, *pwll, *pw1h, *pw1l, *pw2h, *pw2l;
    cudaGetSymbolAddress((void**)&pwlh, g_wlhi);
    cudaGetSymbolAddress((void**)&pwll, g_wllo);
    cudaGetSymbolAddress((void**)&pw1h, g_w1hi);
    cudaGetSymbolAddress((void**)&pw1l, g_w1lo);
    cudaGetSymbolAddress((void**)&pw2h, g_w2hi);
    cudaGetSymbolAddress((void**)&pw2l, g_w2lo);

    int dev = 0, nsm = 148;
    cudaGetDevice(&dev);
    cudaDeviceGetAttribute(&nsm, cudaDevAttrMultiProcessorCount, dev);

    cudaFuncSetAttribute(gemm_mma<0>, cudaFuncAttributeMaxDynamicSharedMemorySize, SMEM_MMA);
    cudaFuncSetAttribute(gemm_mma<1>, cudaFuncAttributeMaxDynamicSharedMemorySize, SMEM_MMA);
    cudaFuncSetAttribute(gemm_mma<2>, cudaFuncAttributeMaxDynamicSharedMemorySize, SMEM_MMA);

    // 1) zero accumulators; split+layout weights
    zero_kernel<<<2500, 256>>>();
    wprep_kernel<<<(NF * NF + 255) / 256, 256>>>(W_lin, W1, W2);
    // 2) segment sum
    seg_sum_kernel<<<(M + 255) / 256, 128>>>(x, batch, M);
    // 3) P = S @ W_lin  (HMMA, fused BN0 stats)
    gemm_mma<0><<<nsm, 256, SMEM_MMA>>>(pS, pwlh, pwll, nullptr, nullptr, nullptr,
                                        nullptr, nullptr, pP, pstat0, NGRAPHS, ntiles_sml);
    // 4) BN0 scale/shift, T = relu(BN(P))
    bn_prep_kernel<<<1, NF>>>(pstat0, pstat0 + NF, (float)NGRAPHS, bn_g, bn_b, psc0, psh0);
    make_T_kernel<<<(NGRAPHS * NF + 255) / 256, 256>>>();
    // 5) H1 = (x + T[batch]) @ W1 + b1  (HMMA, fused BN1 stats)
    gemm_mma<1><<<nsm, 256, SMEM_MMA>>>(x, pw1h, pw1l, b1, pT, batch,
                                        nullptr, nullptr, pH1, pstat1, M, ntiles_big);
    // 6) BN1 scale/shift
    bn_prep_kernel<<<1, NF>>>(pstat1, pstat1 + NF, (float)M, bn1_g, bn1_b, psc1, psh1);
    // 7) out = relu(BN(H1)) @ W2 + b2  (HMMA)
    gemm_mma<2><<<nsm, 256, SMEM_MMA>>>(pH1, pw2h, pw2l, b2, nullptr, nullptr,
                                        psc1, psh1, out, nullptr, M, ntiles_big);
}